// round 2
// baseline (speedup 1.0000x reference)
#include <cuda_runtime.h>

#define S   256
#define C   5
#define B   64
#define SPLIT 4
#define GRAYW (0.2989f + 0.5870f + 0.1140f)

// Scratch: per-(image,channel) weighted sums for the mean. No device allocation allowed.
__device__ float g_sums[B * C];

__global__ void zero_sums_kernel() {
    int i = blockIdx.x * blockDim.x + threadIdx.x;
    if (i < B * C) g_sums[i] = 0.0f;
}

__device__ __forceinline__ void get_params(int b,
                                           const float* __restrict__ off_frac,
                                           const int* __restrict__ crop_size,
                                           const int* __restrict__ do_crop,
                                           float& scale, float& off0, float& off1) {
    bool dc = do_crop[b] != 0;
    float size_f = dc ? (float)crop_size[b] : (float)S;
    scale = size_f / (float)S;
    float span = (float)S - size_f + 1.0f;
    off0 = dc ? floorf(off_frac[2 * b + 0] * span) : 0.0f;
    off1 = dc ? floorf(off_frac[2 * b + 1] * span) : 0.0f;
}

// ---------------------------------------------------------------------------
// K1: per-(b,c) weighted mean of the resampled image.
// mean = (1/S^2) * sum_{i,j} img[i,j,c] * W0[i] * W1[j]
// where W0/W1 are the bilinear weight histograms of the row/col coordinate maps.
// grid = (B, SPLIT), block = 256 threads (one per column).
// ---------------------------------------------------------------------------
__global__ __launch_bounds__(256) void mean_kernel(
    const float* __restrict__ img,
    const float* __restrict__ off_frac,
    const int* __restrict__ crop_size,
    const int* __restrict__ do_crop)
{
    __shared__ float W0[S];
    __shared__ float W1[S];

    const int b = blockIdx.x;
    const int slab = blockIdx.y;
    const int t = threadIdx.x;

    float scale, off0, off1;
    get_params(b, off_frac, crop_size, do_crop, scale, off0, off1);

    W0[t] = 0.0f;
    W1[t] = 0.0f;
    __syncthreads();

    // Each thread scatters the bilinear weights of output index t (both axes).
    {
        float base = ((float)t + 0.5f) * scale - 0.5f;

        float c0 = base + off0;
        float f0 = floorf(c0);
        int  i0 = min(max((int)f0, 0), S - 1);
        int  i1 = min(max((int)f0 + 1, 0), S - 1);
        float fy = c0 - f0;
        atomicAdd(&W0[i0], 1.0f - fy);
        atomicAdd(&W0[i1], fy);

        float c1 = base + off1;
        float f1 = floorf(c1);
        int  j0 = min(max((int)f1, 0), S - 1);
        int  j1 = min(max((int)f1 + 1, 0), S - 1);
        float fx = c1 - f1;
        atomicAdd(&W1[j0], 1.0f - fx);
        atomicAdd(&W1[j1], fx);
    }
    __syncthreads();

    float acc0 = 0.f, acc1 = 0.f, acc2 = 0.f, acc3 = 0.f, acc4 = 0.f;
    const float w1t = W1[t];

    const float* base = img + (size_t)b * S * S * C;
    const int row0  = slab * (S / SPLIT);
    const int row_end = row0 + (S / SPLIT);

    if (w1t != 0.0f) {
        for (int i = row0; i < row_end; i++) {
            float w = W0[i];
            if (w == 0.0f) continue;   // uniform across block (no divergence)
            w *= w1t;
            const float* p = base + (size_t)i * S * C + t * C;
            acc0 += p[0] * w;
            acc1 += p[1] * w;
            acc2 += p[2] * w;
            acc3 += p[3] * w;
            acc4 += p[4] * w;
        }
    }

    // warp-reduce then global atomics (8 warps * 5 channels per block)
    float accs[C] = {acc0, acc1, acc2, acc3, acc4};
#pragma unroll
    for (int c = 0; c < C; c++) {
        float v = accs[c];
#pragma unroll
        for (int o = 16; o > 0; o >>= 1)
            v += __shfl_down_sync(0xffffffffu, v, o);
        if ((t & 31) == 0)
            atomicAdd(&g_sums[b * C + c], v);
    }
}

// ---------------------------------------------------------------------------
// K2: full augmentation as a single gather + epilogue.
// out[b,y,x,c] = ((v - m)*contrast + m + bright) * GRAY
// with (y,x) inverse-mapped through rot90(k) and flip into resampled coords,
// and v the 4-tap bilinear sample (axis-0 lerp first, matching the reference).
// grid = (S, B), block = 256 threads (one per x).
// ---------------------------------------------------------------------------
__global__ __launch_bounds__(256) void aug_kernel(
    const float* __restrict__ img,
    const float* __restrict__ off_frac,
    const float* __restrict__ bright,
    const float* __restrict__ contrast,
    const int* __restrict__ crop_size,
    const int* __restrict__ do_crop,
    const int* __restrict__ flip,
    const int* __restrict__ rot_k,
    float* __restrict__ out)
{
    const int b = blockIdx.y;
    const int y = blockIdx.x;
    const int x = threadIdx.x;

    float scale, off0, off1;
    get_params(b, off_frac, crop_size, do_crop, scale, off0, off1);

    const int k = rot_k[b] & 3;
    const bool fl = flip[b] != 0;

    // inverse of: flip_lr then rot90(k)
    int ry, rx;
    switch (k) {
        case 0:  ry = y;         rx = x;         break;
        case 1:  ry = x;         rx = S - 1 - y; break;
        case 2:  ry = S - 1 - y; rx = S - 1 - x; break;
        default: ry = S - 1 - x; rx = y;         break;
    }
    if (fl) rx = S - 1 - rx;

    const float cy = ((float)ry + 0.5f) * scale - 0.5f + off0;
    const float cx = ((float)rx + 0.5f) * scale - 0.5f + off1;
    const float fyf = floorf(cy), fxf = floorf(cx);
    const int i0 = min(max((int)fyf, 0), S - 1);
    const int i1 = min(max((int)fyf + 1, 0), S - 1);
    const int j0 = min(max((int)fxf, 0), S - 1);
    const int j1 = min(max((int)fxf + 1, 0), S - 1);
    const float ty = cy - fyf;
    const float tx = cx - fxf;

    const float* r0 = img + (size_t)b * S * S * C + (size_t)i0 * S * C;
    const float* r1 = img + (size_t)b * S * S * C + (size_t)i1 * S * C;
    const float* p00 = r0 + j0 * C;
    const float* p01 = r0 + j1 * C;
    const float* p10 = r1 + j0 * C;
    const float* p11 = r1 + j1 * C;

    const float inv_area = 1.0f / (float)(S * S);
    float* o = out + (((size_t)b * S + y) * S + x) * C;

#pragma unroll
    for (int c = 0; c < C; c++) {
        // axis-0 lerp first, then axis-1 (matches reference association)
        float a = p00[c] + (p10[c] - p00[c]) * ty;
        float bb = p01[c] + (p11[c] - p01[c]) * ty;
        float v = a + (bb - a) * tx;

        float m = g_sums[b * C + c] * inv_area;
        o[c] = ((v - m) * contrast[b * C + c] + m + bright[b * C + c]) * GRAYW;
    }
}

extern "C" void kernel_launch(void* const* d_in, const int* in_sizes, int n_in,
                              void* d_out, int out_size) {
    const float* crops     = (const float*)d_in[0];
    const float* off_frac  = (const float*)d_in[1];
    const float* bright    = (const float*)d_in[2];
    const float* contrast  = (const float*)d_in[3];
    const int*   crop_size = (const int*)d_in[4];
    const int*   do_crop   = (const int*)d_in[5];
    const int*   flip      = (const int*)d_in[6];
    const int*   rot_k     = (const int*)d_in[7];
    float*       out       = (float*)d_out;

    zero_sums_kernel<<<1, B * C>>>();
    mean_kernel<<<dim3(B, SPLIT), 256>>>(crops, off_frac, crop_size, do_crop);
    aug_kernel<<<dim3(S, B), 256>>>(crops, off_frac, bright, contrast,
                                    crop_size, do_crop, flip, rot_k, out);
}

// round 3
// speedup vs baseline: 2.1887x; 2.1887x over previous
#include <cuda_runtime.h>

#define S     256
#define C     5
#define B     64
#define SPLIT 4
#define TX    32
#define TY    32
#define PITCH 171        // smem row pitch in floats; gcd(171,32)=1 -> conflict-free
#define MAXH  35
#define GRAYW (0.2989f + 0.5870f + 0.1140f)

// Per-(image,slab,channel) partial weighted sums. No device allocation allowed.
__device__ float g_part[B * SPLIT * C];

__device__ __forceinline__ void get_params(int b,
                                           const float* __restrict__ off_frac,
                                           const int* __restrict__ crop_size,
                                           const int* __restrict__ do_crop,
                                           float& scale, float& off0, float& off1) {
    bool dc = do_crop[b] != 0;
    float size_f = dc ? (float)crop_size[b] : (float)S;
    scale = size_f / (float)S;
    float span = (float)S - size_f + 1.0f;
    off0 = dc ? floorf(off_frac[2 * b + 0] * span) : 0.0f;
    off1 = dc ? floorf(off_frac[2 * b + 1] * span) : 0.0f;
}

__device__ __forceinline__ void inv_map(int k, bool fl, int y, int x, int& ry, int& rx) {
    switch (k) {
        case 0:  ry = y;         rx = x;         break;
        case 1:  ry = x;         rx = S - 1 - y; break;
        case 2:  ry = S - 1 - y; rx = S - 1 - x; break;
        default: ry = S - 1 - x; rx = y;         break;
    }
    if (fl) rx = S - 1 - rx;
}

// ---------------------------------------------------------------------------
// K1: per-(b,slab,c) partial weighted mean of the resampled image.
// mean = (1/S^2) * sum_{i,j} img[i,j,c] * W0[i] * W1[j]
// grid = (B, SPLIT), block = 256 threads (one per column).
// ---------------------------------------------------------------------------
__global__ __launch_bounds__(256) void mean_kernel(
    const float* __restrict__ img,
    const float* __restrict__ off_frac,
    const int* __restrict__ crop_size,
    const int* __restrict__ do_crop)
{
    __shared__ float W0[S];
    __shared__ float W1[S];
    __shared__ float red[8][C];

    const int b = blockIdx.x;
    const int slab = blockIdx.y;
    const int t = threadIdx.x;

    float scale, off0, off1;
    get_params(b, off_frac, crop_size, do_crop, scale, off0, off1);

    W0[t] = 0.0f;
    W1[t] = 0.0f;
    __syncthreads();

    {
        float base = ((float)t + 0.5f) * scale - 0.5f;

        float c0 = base + off0;
        float f0 = floorf(c0);
        int  i0 = min(max((int)f0, 0), S - 1);
        int  i1 = min(max((int)f0 + 1, 0), S - 1);
        float fy = c0 - f0;
        atomicAdd(&W0[i0], 1.0f - fy);
        atomicAdd(&W0[i1], fy);

        float c1 = base + off1;
        float f1 = floorf(c1);
        int  j0 = min(max((int)f1, 0), S - 1);
        int  j1 = min(max((int)f1 + 1, 0), S - 1);
        float fx = c1 - f1;
        atomicAdd(&W1[j0], 1.0f - fx);
        atomicAdd(&W1[j1], fx);
    }
    __syncthreads();

    float acc[C] = {0.f, 0.f, 0.f, 0.f, 0.f};
    const float w1t = W1[t];

    const float* base = img + (size_t)b * S * S * C;
    const int row0 = slab * (S / SPLIT);
    const int row_end = row0 + (S / SPLIT);

    if (w1t != 0.0f) {
        for (int i = row0; i < row_end; i++) {
            float w = W0[i];
            if (w == 0.0f) continue;   // uniform across block
            w *= w1t;
            const float* p = base + (size_t)i * S * C + t * C;
#pragma unroll
            for (int c = 0; c < C; c++) acc[c] += p[c] * w;
        }
    }

#pragma unroll
    for (int c = 0; c < C; c++) {
        float v = acc[c];
#pragma unroll
        for (int o = 16; o > 0; o >>= 1)
            v += __shfl_down_sync(0xffffffffu, v, o);
        if ((t & 31) == 0) red[t >> 5][c] = v;
    }
    __syncthreads();

    if (t < C) {
        float s = 0.f;
#pragma unroll
        for (int w = 0; w < 8; w++) s += red[w][t];
        g_part[(b * SPLIT + slab) * C + t] = s;
    }
}

// ---------------------------------------------------------------------------
// K2: tiled gather + epilogue. Each block = one 32x32 output tile of image b.
// Source footprint rect is loaded coalesced into smem; rotated/flipped/
// resampled reads hit smem; output writes are coalesced.
// grid = (S/TX, S/TY, B), block = 256.
// ---------------------------------------------------------------------------
__global__ __launch_bounds__(256) void aug_kernel(
    const float* __restrict__ img,
    const float* __restrict__ off_frac,
    const float* __restrict__ bright,
    const float* __restrict__ contrast,
    const int* __restrict__ crop_size,
    const int* __restrict__ do_crop,
    const int* __restrict__ flip,
    const int* __restrict__ rot_k,
    float* __restrict__ out)
{
    __shared__ float tile[MAXH * PITCH];
    __shared__ float msh[C], csh[C], bsh[C];

    const int b  = blockIdx.z;
    const int x0 = blockIdx.x * TX;
    const int y0 = blockIdx.y * TY;
    const int t  = threadIdx.x;

    float scale, off0, off1;
    get_params(b, off_frac, crop_size, do_crop, scale, off0, off1);
    const int k = rot_k[b] & 3;
    const bool fl = flip[b] != 0;

    // Source footprint: map the 4 tile corners; per-axis monotone map -> rect.
    int ry_min = S, ry_max = 0, rx_min = S, rx_max = 0;
#pragma unroll
    for (int cn = 0; cn < 4; cn++) {
        int yy = (cn & 1) ? (y0 + TY - 1) : y0;
        int xx = (cn & 2) ? (x0 + TX - 1) : x0;
        int ry, rx;
        inv_map(k, fl, yy, xx, ry, rx);
        ry_min = min(ry_min, ry); ry_max = max(ry_max, ry);
        rx_min = min(rx_min, rx); rx_max = max(rx_max, rx);
    }
    const float cy_min = ((float)ry_min + 0.5f) * scale - 0.5f + off0;
    const float cy_max = ((float)ry_max + 0.5f) * scale - 0.5f + off0;
    const float cx_min = ((float)rx_min + 0.5f) * scale - 0.5f + off1;
    const float cx_max = ((float)rx_max + 0.5f) * scale - 0.5f + off1;
    const int i_min = min(max((int)floorf(cy_min), 0), S - 1);
    const int i_max = min(max((int)floorf(cy_max) + 1, 0), S - 1);
    const int j_min = min(max((int)floorf(cx_min), 0), S - 1);
    const int j_max = min(max((int)floorf(cx_max) + 1, 0), S - 1);
    const int srcH = i_max - i_min + 1;
    const int srcWc = (j_max - j_min + 1) * C;   // row segment length in floats

    // Per-channel epilogue params
    if (t < C) {
        const float inv_area = 1.0f / (float)(S * S);
        float s = 0.f;
#pragma unroll
        for (int p = 0; p < SPLIT; p++) s += g_part[(b * SPLIT + p) * C + t];
        msh[t] = s * inv_area;
        csh[t] = contrast[b * C + t];
        bsh[t] = bright[b * C + t];
    }

    // Coalesced load of the source rect into smem (warp per row, strided).
    {
        const int wid = t >> 5, lane = t & 31;
        const float* base = img + (size_t)b * S * S * C + (size_t)i_min * S * C + j_min * C;
        for (int r = wid; r < srcH; r += 8) {
            const float* src = base + (size_t)r * S * C;
            float* dst = tile + r * PITCH;
            for (int e = lane; e < srcWc; e += 32)
                dst[e] = src[e];
        }
    }
    __syncthreads();

    // Compute 4 output pixels per thread, row-major in the output tile.
#pragma unroll
    for (int q = 0; q < 4; q++) {
        const int p  = t + q * 256;
        const int py = p >> 5;
        const int px = p & 31;
        const int y = y0 + py, x = x0 + px;

        int ry, rx;
        inv_map(k, fl, y, x, ry, rx);

        const float cy = ((float)ry + 0.5f) * scale - 0.5f + off0;
        const float cx = ((float)rx + 0.5f) * scale - 0.5f + off1;
        const float fyf = floorf(cy), fxf = floorf(cx);
        const int i0 = min(max((int)fyf, 0), S - 1);
        const int i1 = min(max((int)fyf + 1, 0), S - 1);
        const int j0 = min(max((int)fxf, 0), S - 1);
        const int j1 = min(max((int)fxf + 1, 0), S - 1);
        const float ty = cy - fyf;
        const float tx = cx - fxf;

        const float* r0 = tile + (i0 - i_min) * PITCH;
        const float* r1 = tile + (i1 - i_min) * PITCH;
        const int c0 = (j0 - j_min) * C;
        const int c1 = (j1 - j_min) * C;

        float* o = out + (((size_t)b * S + y) * S + x) * C;
#pragma unroll
        for (int c = 0; c < C; c++) {
            float p00 = r0[c0 + c], p01 = r0[c1 + c];
            float p10 = r1[c0 + c], p11 = r1[c1 + c];
            float a  = p00 + (p10 - p00) * ty;
            float bb = p01 + (p11 - p01) * ty;
            float v  = a + (bb - a) * tx;
            o[c] = ((v - msh[c]) * csh[c] + msh[c] + bsh[c]) * GRAYW;
        }
    }
}

extern "C" void kernel_launch(void* const* d_in, const int* in_sizes, int n_in,
                              void* d_out, int out_size) {
    const float* crops     = (const float*)d_in[0];
    const float* off_frac  = (const float*)d_in[1];
    const float* bright    = (const float*)d_in[2];
    const float* contrast  = (const float*)d_in[3];
    const int*   crop_size = (const int*)d_in[4];
    const int*   do_crop   = (const int*)d_in[5];
    const int*   flip      = (const int*)d_in[6];
    const int*   rot_k     = (const int*)d_in[7];
    float*       out       = (float*)d_out;

    mean_kernel<<<dim3(B, SPLIT), 256>>>(crops, off_frac, crop_size, do_crop);
    aug_kernel<<<dim3(S / TX, S / TY, B), 256>>>(crops, off_frac, bright, contrast,
                                                 crop_size, do_crop, flip, rot_k, out);
}

// round 4
// speedup vs baseline: 2.7310x; 1.2478x over previous
#include <cuda_runtime.h>

#define S     256
#define C     5
#define SC    (S * C)          // 1280 floats per row
#define B     64
#define SPLIT 8
#define TX    32
#define TY    32
#define PITCH 181              // odd -> conflict-free for lane strides 5 and PITCH
#define MAXH  35
#define GRAYW (0.2989f + 0.5870f + 0.1140f)

// Per-(image,slab,channel) partial weighted sums. No device allocation allowed.
__device__ float g_part[B * SPLIT * C];

__device__ __forceinline__ void get_params(int b,
                                           const float* __restrict__ off_frac,
                                           const int* __restrict__ crop_size,
                                           const int* __restrict__ do_crop,
                                           bool& dc, float& scale, float& off0, float& off1) {
    dc = do_crop[b] != 0;
    float size_f = dc ? (float)crop_size[b] : (float)S;
    scale = size_f / (float)S;
    float span = (float)S - size_f + 1.0f;
    off0 = dc ? floorf(off_frac[2 * b + 0] * span) : 0.0f;
    off1 = dc ? floorf(off_frac[2 * b + 1] * span) : 0.0f;
}

__device__ __forceinline__ void inv_map(int k, bool fl, int y, int x, int& ry, int& rx) {
    switch (k) {
        case 0:  ry = y;         rx = x;         break;
        case 1:  ry = x;         rx = S - 1 - y; break;
        case 2:  ry = S - 1 - y; rx = S - 1 - x; break;
        default: ry = S - 1 - x; rx = y;         break;
    }
    if (fl) rx = S - 1 - rx;
}

// ---------------------------------------------------------------------------
// K1: per-(b,slab,c) partial weighted mean of the resampled image.
// mean = (1/S^2) * sum_{i,j} img[i,j,c] * W0[i] * W1[j]
// Thread owns 4 pixels (20 floats = 5 x float4 per row). grid (B, SPLIT).
// ---------------------------------------------------------------------------
__global__ __launch_bounds__(256) void mean_kernel(
    const float* __restrict__ img,
    const float* __restrict__ off_frac,
    const int* __restrict__ crop_size,
    const int* __restrict__ do_crop)
{
    __shared__ float W0[S];
    __shared__ float W1[S];
    __shared__ float red[8][C];

    const int b = blockIdx.x;
    const int slab = blockIdx.y;
    const int t = threadIdx.x;

    bool dc; float scale, off0, off1;
    get_params(b, off_frac, crop_size, do_crop, dc, scale, off0, off1);

    W0[t] = 0.0f;
    W1[t] = 0.0f;
    __syncthreads();

    {
        float base = ((float)t + 0.5f) * scale - 0.5f;

        float c0 = base + off0;
        float f0 = floorf(c0);
        int  i0 = min(max((int)f0, 0), S - 1);
        int  i1 = min(max((int)f0 + 1, 0), S - 1);
        float fy = c0 - f0;
        atomicAdd(&W0[i0], 1.0f - fy);
        atomicAdd(&W0[i1], fy);

        float c1 = base + off1;
        float f1 = floorf(c1);
        int  j0 = min(max((int)f1, 0), S - 1);
        int  j1 = min(max((int)f1 + 1, 0), S - 1);
        float fx = c1 - f1;
        atomicAdd(&W1[j0], 1.0f - fx);
        atomicAdd(&W1[j1], fx);
    }
    __syncthreads();

    // thread t -> pixel group g (4 px), row lane r (0..3); warp-uniform r.
    const int g = t & 63;
    const int r = t >> 6;
    const int px0 = g * 4;
    float w1v0 = W1[px0], w1v1 = W1[px0 + 1], w1v2 = W1[px0 + 2], w1v3 = W1[px0 + 3];

    float acc[C] = {0.f, 0.f, 0.f, 0.f, 0.f};
    const int rows = S / SPLIT;
    const int row0 = slab * rows;
    const float* base = img + (size_t)b * S * SC / S * S; // b * S*S*C
    // (simplify): base = img + (size_t)b * S * S * C
    base = img + (size_t)b * S * S * C;

    for (int it = 0; it < rows / 4; it++) {
        const int i = row0 + r + it * 4;
        const float w0 = W0[i];
        if (w0 == 0.0f) continue;                     // warp-uniform
        const float4* p4 = (const float4*)(base + (size_t)i * SC + px0 * C);
        float4 v0 = p4[0], v1 = p4[1], v2 = p4[2], v3 = p4[3], v4 = p4[4];
        float ww0 = w0 * w1v0, ww1 = w0 * w1v1, ww2 = w0 * w1v2, ww3 = w0 * w1v3;
        acc[0] += v0.x * ww0; acc[1] += v0.y * ww0; acc[2] += v0.z * ww0; acc[3] += v0.w * ww0;
        acc[4] += v1.x * ww0;
        acc[0] += v1.y * ww1; acc[1] += v1.z * ww1; acc[2] += v1.w * ww1;
        acc[3] += v2.x * ww1; acc[4] += v2.y * ww1;
        acc[0] += v2.z * ww2; acc[1] += v2.w * ww2; acc[2] += v3.x * ww2;
        acc[3] += v3.y * ww2; acc[4] += v3.z * ww2;
        acc[0] += v3.w * ww3; acc[1] += v4.x * ww3; acc[2] += v4.y * ww3;
        acc[3] += v4.z * ww3; acc[4] += v4.w * ww3;
    }

#pragma unroll
    for (int c = 0; c < C; c++) {
        float v = acc[c];
#pragma unroll
        for (int o = 16; o > 0; o >>= 1)
            v += __shfl_down_sync(0xffffffffu, v, o);
        if ((t & 31) == 0) red[t >> 5][c] = v;
    }
    __syncthreads();

    if (t < C) {
        float s = 0.f;
#pragma unroll
        for (int w = 0; w < 8; w++) s += red[w][t];
        g_part[(b * SPLIT + slab) * C + t] = s;
    }
}

// ---------------------------------------------------------------------------
// K2: tiled gather + fused epilogue. Block = 32x32 output tile of image b.
// Vectorized (float4) coalesced load of the source rect into smem.
// ---------------------------------------------------------------------------
__global__ __launch_bounds__(256) void aug_kernel(
    const float* __restrict__ img,
    const float* __restrict__ off_frac,
    const float* __restrict__ bright,
    const float* __restrict__ contrast,
    const int* __restrict__ crop_size,
    const int* __restrict__ do_crop,
    const int* __restrict__ flip,
    const int* __restrict__ rot_k,
    float* __restrict__ out)
{
    __shared__ float tile[MAXH * PITCH];
    __shared__ float Ash[C], Dsh[C];

    const int b  = blockIdx.z;
    const int x0 = blockIdx.x * TX;
    const int y0 = blockIdx.y * TY;
    const int t  = threadIdx.x;

    bool dc; float scale, off0, off1;
    get_params(b, off_frac, crop_size, do_crop, dc, scale, off0, off1);
    const int k = rot_k[b] & 3;
    const bool fl = flip[b] != 0;

    // Source footprint rect (per-axis monotone map -> rect from corners).
    int ry_min = S, ry_max = 0, rx_min = S, rx_max = 0;
#pragma unroll
    for (int cn = 0; cn < 4; cn++) {
        int yy = (cn & 1) ? (y0 + TY - 1) : y0;
        int xx = (cn & 2) ? (x0 + TX - 1) : x0;
        int ry, rx;
        inv_map(k, fl, yy, xx, ry, rx);
        ry_min = min(ry_min, ry); ry_max = max(ry_max, ry);
        rx_min = min(rx_min, rx); rx_max = max(rx_max, rx);
    }
    const float cy_min = ((float)ry_min + 0.5f) * scale - 0.5f + off0;
    const float cy_max = ((float)ry_max + 0.5f) * scale - 0.5f + off0;
    const float cx_min = ((float)rx_min + 0.5f) * scale - 0.5f + off1;
    const float cx_max = ((float)rx_max + 0.5f) * scale - 0.5f + off1;
    const int i_min = min(max((int)floorf(cy_min), 0), S - 1);
    const int i_max = min(max((int)floorf(cy_max) + 1, 0), S - 1);
    const int j_min = min(max((int)floorf(cx_min), 0), S - 1);
    const int j_max = min(max((int)floorf(cx_max) + 1, 0), S - 1);
    const int srcH = i_max - i_min + 1;

    // 16B-aligned float range within each source row.
    const int f_lo = j_min * C;
    const int f_hi = j_max * C + C;
    const int g_start = f_lo & ~3;
    const int width_f = ((f_hi + 3) & ~3) - g_start;    // <= 176

    // Fused per-channel epilogue params: o = v*A + D
    if (t < C) {
        const float inv_area = 1.0f / (float)(S * S);
        float s = 0.f;
#pragma unroll
        for (int p = 0; p < SPLIT; p++) s += g_part[(b * SPLIT + p) * C + t];
        float m = s * inv_area;
        float cc = contrast[b * C + t];
        Ash[t] = cc * GRAYW;
        Dsh[t] = (m * (1.0f - cc) + bright[b * C + t]) * GRAYW;
    }

    // Vectorized coalesced load of the rect (warp per row, float4).
    {
        const int wid = t >> 5, lane = t & 31;
        const float* base = img + (size_t)b * S * SC + (size_t)i_min * SC + g_start;
        for (int r = wid; r < srcH; r += 8) {
            const float* grow = base + (size_t)r * SC;
            float* srow = tile + r * PITCH;
            for (int e4 = lane * 4; e4 < width_f; e4 += 128) {
                float4 v = *(const float4*)(grow + e4);
                srow[e4]     = v.x;
                srow[e4 + 1] = v.y;
                srow[e4 + 2] = v.z;
                srow[e4 + 3] = v.w;
            }
        }
    }
    __syncthreads();

    if (!dc) {
        // Fast path: scale==1, off==0 -> bilinear degenerates to exact pixel.
#pragma unroll
        for (int q = 0; q < 4; q++) {
            const int p  = t + q * 256;
            const int py = p >> 5;
            const int px = p & 31;
            const int y = y0 + py, x = x0 + px;
            int ry, rx;
            inv_map(k, fl, y, x, ry, rx);
            const float* src = tile + (ry - i_min) * PITCH + (rx * C - g_start);
            float* o = out + (((size_t)b * S + y) * S + x) * C;
#pragma unroll
            for (int c = 0; c < C; c++)
                o[c] = src[c] * Ash[c] + Dsh[c];
        }
    } else {
#pragma unroll
        for (int q = 0; q < 4; q++) {
            const int p  = t + q * 256;
            const int py = p >> 5;
            const int px = p & 31;
            const int y = y0 + py, x = x0 + px;

            int ry, rx;
            inv_map(k, fl, y, x, ry, rx);

            const float cy = ((float)ry + 0.5f) * scale - 0.5f + off0;
            const float cx = ((float)rx + 0.5f) * scale - 0.5f + off1;
            const float fyf = floorf(cy), fxf = floorf(cx);
            const int i0 = min(max((int)fyf, 0), S - 1);
            const int i1 = min(max((int)fyf + 1, 0), S - 1);
            const int j0 = min(max((int)fxf, 0), S - 1);
            const int j1 = min(max((int)fxf + 1, 0), S - 1);
            const float ty = cy - fyf;
            const float tx = cx - fxf;

            const float* r0 = tile + (i0 - i_min) * PITCH;
            const float* r1 = tile + (i1 - i_min) * PITCH;
            const int c0 = j0 * C - g_start;
            const int c1 = j1 * C - g_start;

            float* o = out + (((size_t)b * S + y) * S + x) * C;
#pragma unroll
            for (int c = 0; c < C; c++) {
                float p00 = r0[c0 + c], p01 = r0[c1 + c];
                float p10 = r1[c0 + c], p11 = r1[c1 + c];
                float a  = p00 + (p10 - p00) * ty;
                float bb = p01 + (p11 - p01) * ty;
                float v  = a + (bb - a) * tx;
                o[c] = v * Ash[c] + Dsh[c];
            }
        }
    }
}

extern "C" void kernel_launch(void* const* d_in, const int* in_sizes, int n_in,
                              void* d_out, int out_size) {
    const float* crops     = (const float*)d_in[0];
    const float* off_frac  = (const float*)d_in[1];
    const float* bright    = (const float*)d_in[2];
    const float* contrast  = (const float*)d_in[3];
    const int*   crop_size = (const int*)d_in[4];
    const int*   do_crop   = (const int*)d_in[5];
    const int*   flip      = (const int*)d_in[6];
    const int*   rot_k     = (const int*)d_in[7];
    float*       out       = (float*)d_out;

    mean_kernel<<<dim3(B, SPLIT), 256>>>(crops, off_frac, crop_size, do_crop);
    aug_kernel<<<dim3(S / TX, S / TY, B), 256>>>(crops, off_frac, bright, contrast,
                                                 crop_size, do_crop, flip, rot_k, out);
}

// round 5
// speedup vs baseline: 3.0052x; 1.1004x over previous
#include <cuda_runtime.h>

#define S      256
#define C      5
#define SC     (S * C)          // 1280 floats per image row
#define B      64
#define SPLIT  8
#define TX     32
#define TY     32
#define PITCHO 161              // 32*5+1, odd -> conflict-free for strides 5 and PITCHO
#define GRAYW  (0.2989f + 0.5870f + 0.1140f)

// Per-(image,slab,channel) partial weighted sums. No device allocation allowed.
__device__ float g_part[B * SPLIT * C];

__device__ __forceinline__ void get_params(int b,
                                           const float* __restrict__ off_frac,
                                           const int* __restrict__ crop_size,
                                           const int* __restrict__ do_crop,
                                           bool& dc, float& scale, float& off0, float& off1) {
    dc = do_crop[b] != 0;
    float size_f = dc ? (float)crop_size[b] : (float)S;
    scale = size_f / (float)S;
    float span = (float)S - size_f + 1.0f;
    off0 = dc ? floorf(off_frac[2 * b + 0] * span) : 0.0f;
    off1 = dc ? floorf(off_frac[2 * b + 1] * span) : 0.0f;
}

__device__ __forceinline__ void inv_map(int k, bool fl, int y, int x, int& ry, int& rx) {
    switch (k) {
        case 0:  ry = y;         rx = x;         break;
        case 1:  ry = x;         rx = S - 1 - y; break;
        case 2:  ry = S - 1 - y; rx = S - 1 - x; break;
        default: ry = S - 1 - x; rx = y;         break;
    }
    if (fl) rx = S - 1 - rx;
}

// Generic per-pixel sample + fused epilogue, straight from gmem (L2-resident).
__device__ __forceinline__ void sample_px(
    const float* __restrict__ base, bool dc, float scale, float off0, float off1,
    int ry, int rx, const float* Ash, const float* Dsh, float v[C])
{
    if (!dc) {
        const float* s = base + (size_t)ry * SC + rx * C;
#pragma unroll
        for (int c = 0; c < C; c++) v[c] = s[c] * Ash[c] + Dsh[c];
        return;
    }
    const float cy = ((float)ry + 0.5f) * scale - 0.5f + off0;
    const float cx = ((float)rx + 0.5f) * scale - 0.5f + off1;
    const float fyf = floorf(cy), fxf = floorf(cx);
    const int i0 = min(max((int)fyf, 0), S - 1);
    const int i1 = min(max((int)fyf + 1, 0), S - 1);
    const int j0 = min(max((int)fxf, 0), S - 1);
    const int j1 = min(max((int)fxf + 1, 0), S - 1);
    const float ty = cy - fyf;
    const float tx = cx - fxf;

    const float* r0 = base + (size_t)i0 * SC;
    const float* r1 = base + (size_t)i1 * SC;
    const int c0 = j0 * C, c1 = j1 * C;
#pragma unroll
    for (int c = 0; c < C; c++) {
        float p00 = r0[c0 + c], p01 = r0[c1 + c];
        float p10 = r1[c0 + c], p11 = r1[c1 + c];
        float a  = p00 + (p10 - p00) * ty;
        float bb = p01 + (p11 - p01) * ty;
        float vv = a + (bb - a) * tx;
        v[c] = vv * Ash[c] + Dsh[c];
    }
}

// ---------------------------------------------------------------------------
// K1: per-(b,slab,c) partial weighted mean of the resampled image.
// mean = (1/S^2) * sum_{i,j} img[i,j,c] * W0[i] * W1[j]
// ---------------------------------------------------------------------------
__global__ __launch_bounds__(256) void mean_kernel(
    const float* __restrict__ img,
    const float* __restrict__ off_frac,
    const int* __restrict__ crop_size,
    const int* __restrict__ do_crop)
{
    __shared__ float W0[S];
    __shared__ float W1[S];
    __shared__ float red[8][C];

    const int b = blockIdx.x;
    const int slab = blockIdx.y;
    const int t = threadIdx.x;

    bool dc; float scale, off0, off1;
    get_params(b, off_frac, crop_size, do_crop, dc, scale, off0, off1);

    W0[t] = 0.0f;
    W1[t] = 0.0f;
    __syncthreads();

    {
        float base = ((float)t + 0.5f) * scale - 0.5f;

        float c0 = base + off0;
        float f0 = floorf(c0);
        int  i0 = min(max((int)f0, 0), S - 1);
        int  i1 = min(max((int)f0 + 1, 0), S - 1);
        float fy = c0 - f0;
        atomicAdd(&W0[i0], 1.0f - fy);
        atomicAdd(&W0[i1], fy);

        float c1 = base + off1;
        float f1 = floorf(c1);
        int  j0 = min(max((int)f1, 0), S - 1);
        int  j1 = min(max((int)f1 + 1, 0), S - 1);
        float fx = c1 - f1;
        atomicAdd(&W1[j0], 1.0f - fx);
        atomicAdd(&W1[j1], fx);
    }
    __syncthreads();

    const int g = t & 63;          // pixel group (4 px)
    const int r = t >> 6;          // row lane 0..3
    const int px0 = g * 4;
    float w1v0 = W1[px0], w1v1 = W1[px0 + 1], w1v2 = W1[px0 + 2], w1v3 = W1[px0 + 3];

    float acc[C] = {0.f, 0.f, 0.f, 0.f, 0.f};
    const int rows = S / SPLIT;
    const int row0 = slab * rows;
    const float* base = img + (size_t)b * S * S * C;

    for (int it = 0; it < rows / 4; it++) {
        const int i = row0 + r + it * 4;
        const float w0 = W0[i];
        if (w0 == 0.0f) continue;
        const float4* p4 = (const float4*)(base + (size_t)i * SC + px0 * C);
        float4 v0 = p4[0], v1 = p4[1], v2 = p4[2], v3 = p4[3], v4 = p4[4];
        float ww0 = w0 * w1v0, ww1 = w0 * w1v1, ww2 = w0 * w1v2, ww3 = w0 * w1v3;
        acc[0] += v0.x * ww0; acc[1] += v0.y * ww0; acc[2] += v0.z * ww0; acc[3] += v0.w * ww0;
        acc[4] += v1.x * ww0;
        acc[0] += v1.y * ww1; acc[1] += v1.z * ww1; acc[2] += v1.w * ww1;
        acc[3] += v2.x * ww1; acc[4] += v2.y * ww1;
        acc[0] += v2.z * ww2; acc[1] += v2.w * ww2; acc[2] += v3.x * ww2;
        acc[3] += v3.y * ww2; acc[4] += v3.z * ww2;
        acc[0] += v3.w * ww3; acc[1] += v4.x * ww3; acc[2] += v4.y * ww3;
        acc[3] += v4.z * ww3; acc[4] += v4.w * ww3;
    }

#pragma unroll
    for (int c = 0; c < C; c++) {
        float v = acc[c];
#pragma unroll
        for (int o = 16; o > 0; o >>= 1)
            v += __shfl_down_sync(0xffffffffu, v, o);
        if ((t & 31) == 0) red[t >> 5][c] = v;
    }
    __syncthreads();

    if (t < C) {
        float s = 0.f;
#pragma unroll
        for (int w = 0; w < 8; w++) s += red[w][t];
        g_part[(b * SPLIT + slab) * C + t] = s;
    }
}

// ---------------------------------------------------------------------------
// K2: gather + fused epilogue, coalesced on BOTH sides for every rotation.
//  k even: direct streaming gather (rows map to rows) -> no smem, no barrier.
//  k odd : warp-per-output-column gather (coalesced from gmem since ry is
//          warp-constant and rx varies across lanes), results staged in smem,
//          then coalesced row-major writeback.
// grid = (S/TX, S/TY, B), block = 256.
// ---------------------------------------------------------------------------
__global__ __launch_bounds__(256) void aug_kernel(
    const float* __restrict__ img,
    const float* __restrict__ off_frac,
    const float* __restrict__ bright,
    const float* __restrict__ contrast,
    const int* __restrict__ crop_size,
    const int* __restrict__ do_crop,
    const int* __restrict__ flip,
    const int* __restrict__ rot_k,
    float* __restrict__ out)
{
    __shared__ float osh[TY * PITCHO];
    __shared__ float Ash[C], Dsh[C];

    const int b  = blockIdx.z;
    const int x0 = blockIdx.x * TX;
    const int y0 = blockIdx.y * TY;
    const int t  = threadIdx.x;

    bool dc; float scale, off0, off1;
    get_params(b, off_frac, crop_size, do_crop, dc, scale, off0, off1);
    const int k = rot_k[b] & 3;
    const bool fl = flip[b] != 0;

    if (t < C) {
        const float inv_area = 1.0f / (float)(S * S);
        float s = 0.f;
#pragma unroll
        for (int p = 0; p < SPLIT; p++) s += g_part[(b * SPLIT + p) * C + t];
        float m = s * inv_area;
        float cc = contrast[b * C + t];
        Ash[t] = cc * GRAYW;
        Dsh[t] = (m * (1.0f - cc) + bright[b * C + t]) * GRAYW;
    }
    __syncthreads();

    const float* base = img + (size_t)b * S * SC;

    if (!(k & 1)) {
        // ---- Path A: rows map to rows; direct coalesced gather + store ----
#pragma unroll
        for (int q = 0; q < 4; q++) {
            const int p  = t + q * 256;
            const int py = p >> 5;
            const int px = p & 31;
            const int y = y0 + py, x = x0 + px;
            int ry, rx;
            inv_map(k, fl, y, x, ry, rx);
            float v[C];
            sample_px(base, dc, scale, off0, off1, ry, rx, Ash, Dsh, v);
            float* o = out + (((size_t)b * S + y) * S + x) * C;
#pragma unroll
            for (int c = 0; c < C; c++) o[c] = v[c];
        }
    } else {
        // ---- Path B: warp owns an output column (lane = y) ----
        const int w = t >> 5, l = t & 31;
#pragma unroll
        for (int q = 0; q < 4; q++) {
            const int xl = w + q * 8;           // 0..31
            const int x = x0 + xl;
            const int y = y0 + l;
            int ry, rx;
            inv_map(k, fl, y, x, ry, rx);
            float v[C];
            sample_px(base, dc, scale, off0, off1, ry, rx, Ash, Dsh, v);
            float* s = osh + l * PITCHO + xl * C;
#pragma unroll
            for (int c = 0; c < C; c++) s[c] = v[c];
        }
        __syncthreads();
        // coalesced row-major writeback
#pragma unroll
        for (int q = 0; q < 4; q++) {
            const int p  = t + q * 256;
            const int py = p >> 5;
            const int px = p & 31;
            const float* s = osh + py * PITCHO + px * C;
            float* o = out + (((size_t)b * S + y0 + py) * S + x0 + px) * C;
#pragma unroll
            for (int c = 0; c < C; c++) o[c] = s[c];
        }
    }
}

extern "C" void kernel_launch(void* const* d_in, const int* in_sizes, int n_in,
                              void* d_out, int out_size) {
    const float* crops     = (const float*)d_in[0];
    const float* off_frac  = (const float*)d_in[1];
    const float* bright    = (const float*)d_in[2];
    const float* contrast  = (const float*)d_in[3];
    const int*   crop_size = (const int*)d_in[4];
    const int*   do_crop   = (const int*)d_in[5];
    const int*   flip      = (const int*)d_in[6];
    const int*   rot_k     = (const int*)d_in[7];
    float*       out       = (float*)d_out;

    mean_kernel<<<dim3(B, SPLIT), 256>>>(crops, off_frac, crop_size, do_crop);
    aug_kernel<<<dim3(S / TX, S / TY, B), 256>>>(crops, off_frac, bright, contrast,
                                                 crop_size, do_crop, flip, rot_k, out);
}